// round 7
// baseline (speedup 1.0000x reference)
#include <cuda_runtime.h>

#define BB 4
#define CC 256
#define HH 256
#define WW 256
#define RR 64
#define HL 64
#define WL 64
#define LRN (HL*WL)      // 4096
#define PLN (HH*WW)      // 65536

// Scratch (no allocation allowed -> device globals).
__device__ float g_fgp[4][BB*RR*LRN];   // 4 channel-group partials of fg
__device__ float g_ftp[4][BB*RR*LRN];   // 4 channel-group partials of ft
__device__ float g_a [BB*RR*LRN];
__device__ float g_bv[BB*RR*LRN];
__device__ float g_A [BB*CC*LRN];
__device__ float g_B [BB*CC*LRN];
__device__ float g_wrg_t[CC*RR];  // [c][r]
__device__ float g_wrt_t[CC*RR];  // [c][r]
__device__ float g_wua_t[RR*CC];  // [r][o]
__device__ float g_wub_t[RR*CC];  // [r][o]

typedef unsigned long long u64;

__device__ __forceinline__ u64 pack2(float lo, float hi) {
    u64 r; asm("mov.b64 %0, {%1, %2};" : "=l"(r) : "f"(lo), "f"(hi)); return r;
}
__device__ __forceinline__ void fma2(u64& d, u64 a, u64 b) {
    asm("fma.rn.f32x2 %0, %1, %2, %0;" : "+l"(d) : "l"(a), "l"(b));
}
__device__ __forceinline__ float2 unpk(u64 v) {
    float2 f; asm("mov.b64 {%0, %1}, %2;" : "=f"(f.x), "=f"(f.y) : "l"(v)); return f;
}

// K0: transpose weights into GEMM-friendly layouts.
__global__ void k_prep(const float* __restrict__ wrg, const float* __restrict__ wrt,
                       const float* __restrict__ wua, const float* __restrict__ wub) {
    int i = blockIdx.x * 256 + threadIdx.x;   // 16384 total
    if (i < CC*RR) {
        int c = i >> 6, r = i & 63;           // i = c*64 + r
        g_wrg_t[i] = wrg[r*CC + c];
        g_wrt_t[i] = wrt[r*CC + c];
        int rr = i >> 8, o = i & 255;         // i = rr*256 + o
        g_wua_t[i] = wua[o*RR + rr];
        g_wub_t[i] = wub[o*RR + rr];
    }
}

// K12 (fused): bilinear downsample 256->64 + partial C->R projection over a
// 64-channel group, staged GEMM with double-buffered ds tiles.
// 32KB smem -> up to 7 blocks/SM; grid 512 blocks -> ~3.5/SM for latency hiding.
// grid: (64 px-blocks, 4 c-groups, 2 tensors), 256 threads.
__global__ __launch_bounds__(256) void k_ds_proj(const float* __restrict__ enc,
                                                 const float* __restrict__ dec) {
    __shared__ float w_sm[64*RR];        // 16KB: [c_local][r]
    __shared__ float ds_sm[2][8*256];    // 2 x 8KB: [c_chunk_local][px_local]
    int cg = blockIdx.y;
    const float* in  = (blockIdx.z == 0) ? enc     : dec;
    const float* wt  = (blockIdx.z == 0) ? g_wrg_t : g_wrt_t;
    float*       out = (blockIdx.z == 0) ? &g_fgp[cg][0] : &g_ftp[cg][0];
    int t = threadIdx.x;
    for (int i = t; i < 64*RR; i += 256)
        w_sm[i] = wt[(cg*64 + (i >> 6))*RR + (i & 63)];

    int q = blockIdx.x * 256 + t;           // this thread's staging pixel
    int b = q >> 12, rest = q & 4095;
    int x = rest & 63, y = rest >> 6;
    const float* base = in + (size_t)b * CC * PLN + (size_t)cg * 64 * PLN
                           + (size_t)(4*y + 1) * WW + 4*x;

    int rg = t & 3, pg = t >> 2;            // GEMM role: 16 r's, 4 px's

    u64 acc[4][8];
    #pragma unroll
    for (int p = 0; p < 4; p++)
        #pragma unroll
        for (int j = 0; j < 8; j++) acc[p][j] = 0ull;

    for (int ch = 0; ch < 8; ch++) {        // 8 chunks of 8 channels
        int buf = ch & 1;
        // Fill phase: this thread's pixel, 8 channels (16 LDG.128, MLP-friendly).
        #pragma unroll
        for (int cl = 0; cl < 8; cl++) {
            const float* p = base + (size_t)(ch*8 + cl) * PLN;
            float4 r0 = *(const float4*)p;
            float4 r1 = *(const float4*)(p + WW);
            ds_sm[buf][cl*256 + t] = 0.25f * ((r0.y + r0.z) + (r1.y + r1.z));
        }
        __syncthreads();
        // GEMM phase on this buffer; next iteration's fills overlap it.
        #pragma unroll
        for (int cl = 0; cl < 8; cl++) {
            int c = ch*8 + cl;
            float4 d = *(const float4*)(ds_sm[buf] + cl*256 + pg*4);
            u64 d2[4];
            d2[0] = pack2(d.x, d.x); d2[1] = pack2(d.y, d.y);
            d2[2] = pack2(d.z, d.z); d2[3] = pack2(d.w, d.w);
            const ulonglong2* wp = (const ulonglong2*)(w_sm + c*RR + rg*16);
            #pragma unroll
            for (int jj = 0; jj < 4; jj++) {
                ulonglong2 wv = wp[jj];
                #pragma unroll
                for (int p = 0; p < 4; p++) {
                    fma2(acc[p][2*jj    ], wv.x, d2[p]);
                    fma2(acc[p][2*jj + 1], wv.y, d2[p]);
                }
            }
        }
    }
    // Write px4-coalesced: for each of 16 r's, a float4 across the 4 pixels.
    int rest0 = (blockIdx.x * 256 + pg*4) & 4095;
    float* pout = out + (size_t)b * RR * LRN + rest0 + (size_t)(rg*16) * LRN;
    #pragma unroll
    for (int k = 0; k < 8; k++) {
        float2 u0 = unpk(acc[0][k]), u1 = unpk(acc[1][k]);
        float2 u2 = unpk(acc[2][k]), u3 = unpk(acc[3][k]);
        *(float4*)(pout + (size_t)(2*k    ) * LRN) = make_float4(u0.x, u1.x, u2.x, u3.x);
        *(float4*)(pout + (size_t)(2*k + 1) * LRN) = make_float4(u0.y, u1.y, u2.y, u3.y);
    }
}

// K3a: sum 4 channel-group partials, 3x3 zero-padded box mean (/9) + a,b.
__global__ __launch_bounds__(256) void k_guided(const float* __restrict__ eps_p) {
    __shared__ float gs[LRN], ts[LRN];
    int pl = blockIdx.x;  // b*RR + r
    size_t off = (size_t)pl * LRN;
    int t = threadIdx.x;
    for (int i = t; i < LRN; i += 256) {
        gs[i] = (g_fgp[0][off+i] + g_fgp[1][off+i]) + (g_fgp[2][off+i] + g_fgp[3][off+i]);
        ts[i] = (g_ftp[0][off+i] + g_ftp[1][off+i]) + (g_ftp[2][off+i] + g_ftp[3][off+i]);
    }
    __syncthreads();
    float eps = *eps_p;
    const float inv9 = 1.0f / 9.0f;
    for (int i = t; i < LRN; i += 256) {
        int y = i >> 6, x = i & 63;
        float sg = 0.f, st = 0.f, sgg = 0.f, sgt = 0.f;
        #pragma unroll
        for (int dy = -1; dy <= 1; dy++) {
            int yy = y + dy;
            if (yy < 0 || yy > 63) continue;
            #pragma unroll
            for (int dx = -1; dx <= 1; dx++) {
                int xx = x + dx;
                if (xx < 0 || xx > 63) continue;
                float g = gs[yy*64 + xx], v = ts[yy*64 + xx];
                sg += g; st += v; sgg += g*g; sgt += g*v;
            }
        }
        float mg  = sg  * inv9, mt = st * inv9;
        float var = sgg * inv9 - mg*mg;
        float cov = sgt * inv9 - mg*mt;
        float a  = cov / (var + eps);
        float bv = mt - a * mg;
        g_a [off + i] = a;
        g_bv[off + i] = bv;
    }
}

// K3b: R=64 -> C=256 projection at low-res. px-tile=2, o-tile=16,
// A/B split across blockIdx.z (half the accumulators -> high occupancy).
// grid: (32 px-blocks, 16 o-blocks, 2 tensors).
__global__ __launch_bounds__(256) void k_proj_rc() {
    __shared__ float w_sm[RR*16];
    const float* wt  = (blockIdx.z == 0) ? g_wua_t : g_wub_t;
    const float* src = (blockIdx.z == 0) ? g_a     : g_bv;
    float*       dst = (blockIdx.z == 0) ? g_A     : g_B;
    int o0 = blockIdx.y * 16;
    int t = threadIdx.x;
    for (int i = t; i < RR*16; i += 256) {
        int r = i >> 4, j = i & 15;
        w_sm[i] = wt[r*CC + o0 + j];
    }
    __syncthreads();
    int q = (blockIdx.x * 256 + t) * 2;     // 2 consecutive pixels
    int b = q >> 12, rest = q & 4095;
    const float* ps = src + (size_t)b * RR * LRN + rest;
    u64 acc0[8], acc1[8];
    #pragma unroll
    for (int j = 0; j < 8; j++) { acc0[j]=0ull; acc1[j]=0ull; }
    #pragma unroll 4
    for (int r = 0; r < RR; r++) {
        float2 v = *(const float2*)(ps + (size_t)r * LRN);
        u64 v0 = pack2(v.x, v.x), v1 = pack2(v.y, v.y);
        const ulonglong2* wp = (const ulonglong2*)(w_sm + r*16);
        #pragma unroll
        for (int j = 0; j < 4; j++) {
            ulonglong2 w = wp[j];
            fma2(acc0[2*j  ], w.x, v0); fma2(acc1[2*j  ], w.x, v1);
            fma2(acc0[2*j+1], w.y, v0); fma2(acc1[2*j+1], w.y, v1);
        }
    }
    float* od = dst + (size_t)b * CC * LRN + rest;
    #pragma unroll
    for (int j = 0; j < 8; j++) {
        float2 u0 = unpk(acc0[j]), u1 = unpk(acc1[j]);
        *(float2*)(od + (size_t)(o0 + 2*j    ) * LRN) = make_float2(u0.x, u1.x);
        *(float2*)(od + (size_t)(o0 + 2*j + 1) * LRN) = make_float2(u0.y, u1.y);
    }
}

// K4: fused bilinear 64->256 upsample of A,B + out = F_dec + A*F_enc + B.
// One block per (b,c) plane: A,B low-res planes loaded into smem ONCE.
__global__ __launch_bounds__(256) void k_fuse(const float* __restrict__ enc,
                                              const float* __restrict__ dec,
                                              float* __restrict__ out) {
    __shared__ float As[LRN], Bs[LRN];
    int plane = blockIdx.x;
    const float* Ap = g_A + (size_t)plane * LRN;
    const float* Bp = g_B + (size_t)plane * LRN;
    int t = threadIdx.x;
    for (int i = t; i < LRN; i += 256) { As[i] = Ap[i]; Bs[i] = Bp[i]; }
    __syncthreads();
    const float* ep = enc + (size_t)plane * PLN;
    const float* dp = dec + (size_t)plane * PLN;
    float*       op = out + (size_t)plane * PLN;
    int xg = t & 63, ys = t >> 6;
    int cm = max(xg - 1, 0), cp = min(xg + 1, 63);
    for (int yy = 0; yy < 64; yy++) {
        int y = yy*4 + ys;
        float sy = fmaxf((float)y * 0.25f - 0.375f, 0.0f);
        int y0 = (int)sy;
        float wy = sy - (float)y0;
        int y1 = min(y0 + 1, 63);
        const float* rA0 = As + y0*64; const float* rA1 = As + y1*64;
        const float* rB0 = Bs + y0*64; const float* rB1 = Bs + y1*64;
        float am = rA0[cm] + wy * (rA1[cm] - rA0[cm]);
        float ac = rA0[xg] + wy * (rA1[xg] - rA0[xg]);
        float ap = rA0[cp] + wy * (rA1[cp] - rA0[cp]);
        float bm = rB0[cm] + wy * (rB1[cm] - rB0[cm]);
        float bc = rB0[xg] + wy * (rB1[xg] - rB0[xg]);
        float bp = rB0[cp] + wy * (rB1[cp] - rB0[cp]);
        float A0, A1, B0v, B1v;
        if (xg == 0) { A0 = ac; A1 = ac; B0v = bc; B1v = bc; }  // src clamped to 0, w=0
        else {
            A0  = am + 0.625f * (ac - am);
            A1  = am + 0.875f * (ac - am);
            B0v = bm + 0.625f * (bc - bm);
            B1v = bm + 0.875f * (bc - bm);
        }
        float A2 = ac + 0.125f * (ap - ac), A3 = ac + 0.375f * (ap - ac);
        float B2 = bc + 0.125f * (bp - bc), B3 = bc + 0.375f * (bp - bc);
        size_t off = (size_t)y * WW + xg * 4;
        float4 e = *(const float4*)(ep + off);
        float4 d = *(const float4*)(dp + off);
        float4 o;
        o.x = d.x + A0 * e.x + B0v;
        o.y = d.y + A1 * e.y + B1v;
        o.z = d.z + A2 * e.z + B2;
        o.w = d.w + A3 * e.w + B3;
        *(float4*)(op + off) = o;
    }
}

extern "C" void kernel_launch(void* const* d_in, const int* in_sizes, int n_in,
                              void* d_out, int out_size) {
    const float* F_enc = (const float*)d_in[0];
    const float* F_dec = (const float*)d_in[1];
    const float* w_rg  = (const float*)d_in[2];
    const float* w_rt  = (const float*)d_in[3];
    const float* w_ua  = (const float*)d_in[4];
    const float* w_ub  = (const float*)d_in[5];
    const float* eps   = (const float*)d_in[6];
    float* out = (float*)d_out;

    k_prep<<<64, 256>>>(w_rg, w_rt, w_ua, w_ub);
    k_ds_proj<<<dim3(64, 4, 2), 256>>>(F_enc, F_dec);
    k_guided<<<BB*RR, 256>>>(eps);
    k_proj_rc<<<dim3(32, 16, 2), 256>>>();
    k_fuse<<<BB*CC, 256>>>(F_enc, F_dec, out);
}

// round 9
// speedup vs baseline: 1.0116x; 1.0116x over previous
#include <cuda_runtime.h>

#define BB 4
#define CC 256
#define HH 256
#define WW 256
#define RR 64
#define HL 64
#define WL 64
#define LRN (HL*WL)      // 4096
#define PLN (HH*WW)      // 65536

// Scratch (no allocation allowed -> device globals).
__device__ float g_fgp[2][BB*RR*LRN];   // 2 channel-group partials of fg
__device__ float g_ftp[2][BB*RR*LRN];   // 2 channel-group partials of ft
__device__ float g_a [BB*RR*LRN];
__device__ float g_bv[BB*RR*LRN];
__device__ float g_A [BB*CC*LRN];
__device__ float g_B [BB*CC*LRN];
__device__ float g_wrg_t[CC*RR];  // [c][r]
__device__ float g_wrt_t[CC*RR];  // [c][r]
__device__ float g_wua_t[RR*CC];  // [r][o]
__device__ float g_wub_t[RR*CC];  // [r][o]

typedef unsigned long long u64;

__device__ __forceinline__ u64 pack2(float lo, float hi) {
    u64 r; asm("mov.b64 %0, {%1, %2};" : "=l"(r) : "f"(lo), "f"(hi)); return r;
}
__device__ __forceinline__ void fma2(u64& d, u64 a, u64 b) {
    asm("fma.rn.f32x2 %0, %1, %2, %0;" : "+l"(d) : "l"(a), "l"(b));
}
__device__ __forceinline__ float2 unpk(u64 v) {
    float2 f; asm("mov.b64 {%0, %1}, %2;" : "=f"(f.x), "=f"(f.y) : "l"(v)); return f;
}

// K0: transpose weights into GEMM-friendly layouts.
__global__ void k_prep(const float* __restrict__ wrg, const float* __restrict__ wrt,
                       const float* __restrict__ wua, const float* __restrict__ wub) {
    int i = blockIdx.x * 256 + threadIdx.x;   // 16384 total
    if (i < CC*RR) {
        int c = i >> 6, r = i & 63;           // i = c*64 + r
        g_wrg_t[i] = wrg[r*CC + c];
        g_wrt_t[i] = wrt[r*CC + c];
        int rr = i >> 8, o = i & 255;         // i = rr*256 + o
        g_wua_t[i] = wua[o*RR + rr];
        g_wub_t[i] = wub[o*RR + rr];
    }
}

// No-op spacer: shifts ncu's fixed capture window (-s 5 -c 1) by one launch
// so a different kernel (ideally k_fuse) gets profiled.
__global__ void k_noop() {}

// K12 (fused): bilinear downsample 256->64 + partial C->R projection over a
// 128-channel group, staged GEMM with double-buffered ds tiles. (Proven R6.)
// grid: (64 px-blocks, 2 c-groups, 2 tensors), 256 threads, 48KB smem.
__global__ __launch_bounds__(256) void k_ds_proj(const float* __restrict__ enc,
                                                 const float* __restrict__ dec) {
    __shared__ float w_sm[128*RR];       // 32KB: [c_local][r]
    __shared__ float ds_sm[2][8*256];    // 2 x 8KB: [c_chunk_local][px_local]
    int cg = blockIdx.y;
    const float* in  = (blockIdx.z == 0) ? enc     : dec;
    const float* wt  = (blockIdx.z == 0) ? g_wrg_t : g_wrt_t;
    float*       out = (blockIdx.z == 0) ? &g_fgp[cg][0] : &g_ftp[cg][0];
    int t = threadIdx.x;
    for (int i = t; i < 128*RR; i += 256)
        w_sm[i] = wt[(cg*128 + (i >> 6))*RR + (i & 63)];

    int q = blockIdx.x * 256 + t;           // this thread's staging pixel
    int b = q >> 12, rest = q & 4095;
    int x = rest & 63, y = rest >> 6;
    const float* base = in + (size_t)b * CC * PLN + (size_t)cg * 128 * PLN
                           + (size_t)(4*y + 1) * WW + 4*x;

    int rg = t & 3, pg = t >> 2;            // GEMM role: 16 r's, 4 px's

    u64 acc[4][8];
    #pragma unroll
    for (int p = 0; p < 4; p++)
        #pragma unroll
        for (int j = 0; j < 8; j++) acc[p][j] = 0ull;

    for (int ch = 0; ch < 16; ch++) {       // 16 chunks of 8 channels
        int buf = ch & 1;
        #pragma unroll
        for (int cl = 0; cl < 8; cl++) {
            const float* p = base + (size_t)(ch*8 + cl) * PLN;
            float4 r0 = *(const float4*)p;
            float4 r1 = *(const float4*)(p + WW);
            ds_sm[buf][cl*256 + t] = 0.25f * ((r0.y + r0.z) + (r1.y + r1.z));
        }
        __syncthreads();
        #pragma unroll
        for (int cl = 0; cl < 8; cl++) {
            int c = ch*8 + cl;
            float4 d = *(const float4*)(ds_sm[buf] + cl*256 + pg*4);
            u64 d2[4];
            d2[0] = pack2(d.x, d.x); d2[1] = pack2(d.y, d.y);
            d2[2] = pack2(d.z, d.z); d2[3] = pack2(d.w, d.w);
            const ulonglong2* wp = (const ulonglong2*)(w_sm + c*RR + rg*16);
            #pragma unroll
            for (int jj = 0; jj < 4; jj++) {
                ulonglong2 wv = wp[jj];
                #pragma unroll
                for (int p = 0; p < 4; p++) {
                    fma2(acc[p][2*jj    ], wv.x, d2[p]);
                    fma2(acc[p][2*jj + 1], wv.y, d2[p]);
                }
            }
        }
    }
    int rest0 = (blockIdx.x * 256 + pg*4) & 4095;
    float* pout = out + (size_t)b * RR * LRN + rest0 + (size_t)(rg*16) * LRN;
    #pragma unroll
    for (int k = 0; k < 8; k++) {
        float2 u0 = unpk(acc[0][k]), u1 = unpk(acc[1][k]);
        float2 u2 = unpk(acc[2][k]), u3 = unpk(acc[3][k]);
        *(float4*)(pout + (size_t)(2*k    ) * LRN) = make_float4(u0.x, u1.x, u2.x, u3.x);
        *(float4*)(pout + (size_t)(2*k + 1) * LRN) = make_float4(u0.y, u1.y, u2.y, u3.y);
    }
}

// K3a: sum 2 channel-group partials, 3x3 zero-padded box mean (/9) + a,b.
__global__ __launch_bounds__(256) void k_guided(const float* __restrict__ eps_p) {
    __shared__ float gs[LRN], ts[LRN];
    int pl = blockIdx.x;  // b*RR + r
    size_t off = (size_t)pl * LRN;
    int t = threadIdx.x;
    for (int i = t; i < LRN; i += 256) {
        gs[i] = g_fgp[0][off+i] + g_fgp[1][off+i];
        ts[i] = g_ftp[0][off+i] + g_ftp[1][off+i];
    }
    __syncthreads();
    float eps = *eps_p;
    const float inv9 = 1.0f / 9.0f;
    for (int i = t; i < LRN; i += 256) {
        int y = i >> 6, x = i & 63;
        float sg = 0.f, st = 0.f, sgg = 0.f, sgt = 0.f;
        #pragma unroll
        for (int dy = -1; dy <= 1; dy++) {
            int yy = y + dy;
            if (yy < 0 || yy > 63) continue;
            #pragma unroll
            for (int dx = -1; dx <= 1; dx++) {
                int xx = x + dx;
                if (xx < 0 || xx > 63) continue;
                float g = gs[yy*64 + xx], v = ts[yy*64 + xx];
                sg += g; st += v; sgg += g*g; sgt += g*v;
            }
        }
        float mg  = sg  * inv9, mt = st * inv9;
        float var = sgg * inv9 - mg*mg;
        float cov = sgt * inv9 - mg*mt;
        float a  = cov / (var + eps);
        float bv = mt - a * mg;
        g_a [off + i] = a;
        g_bv[off + i] = bv;
    }
}

// K3b: R=64 -> C=256 projection at low-res. px-tile=2, o-tile=16,
// A/B split across blockIdx.z (proven R7: 38.1us).
__global__ __launch_bounds__(256) void k_proj_rc() {
    __shared__ float w_sm[RR*16];
    const float* wt  = (blockIdx.z == 0) ? g_wua_t : g_wub_t;
    const float* src = (blockIdx.z == 0) ? g_a     : g_bv;
    float*       dst = (blockIdx.z == 0) ? g_A     : g_B;
    int o0 = blockIdx.y * 16;
    int t = threadIdx.x;
    for (int i = t; i < RR*16; i += 256) {
        int r = i >> 4, j = i & 15;
        w_sm[i] = wt[r*CC + o0 + j];
    }
    __syncthreads();
    int q = (blockIdx.x * 256 + t) * 2;     // 2 consecutive pixels
    int b = q >> 12, rest = q & 4095;
    const float* ps = src + (size_t)b * RR * LRN + rest;
    u64 acc0[8], acc1[8];
    #pragma unroll
    for (int j = 0; j < 8; j++) { acc0[j]=0ull; acc1[j]=0ull; }
    #pragma unroll 4
    for (int r = 0; r < RR; r++) {
        float2 v = *(const float2*)(ps + (size_t)r * LRN);
        u64 v0 = pack2(v.x, v.x), v1 = pack2(v.y, v.y);
        const ulonglong2* wp = (const ulonglong2*)(w_sm + r*16);
        #pragma unroll
        for (int j = 0; j < 4; j++) {
            ulonglong2 w = wp[j];
            fma2(acc0[2*j  ], w.x, v0); fma2(acc1[2*j  ], w.x, v1);
            fma2(acc0[2*j+1], w.y, v0); fma2(acc1[2*j+1], w.y, v1);
        }
    }
    float* od = dst + (size_t)b * CC * LRN + rest;
    #pragma unroll
    for (int j = 0; j < 8; j++) {
        float2 u0 = unpk(acc0[j]), u1 = unpk(acc1[j]);
        *(float2*)(od + (size_t)(o0 + 2*j    ) * LRN) = make_float2(u0.x, u1.x);
        *(float2*)(od + (size_t)(o0 + 2*j + 1) * LRN) = make_float2(u0.y, u1.y);
    }
}

// K4: fused bilinear 64->256 upsample of A,B + out = F_dec + A*F_enc + B.
__global__ __launch_bounds__(256) void k_fuse(const float* __restrict__ enc,
                                              const float* __restrict__ dec,
                                              float* __restrict__ out) {
    __shared__ float As[LRN], Bs[LRN];
    int plane = blockIdx.x;
    const float* Ap = g_A + (size_t)plane * LRN;
    const float* Bp = g_B + (size_t)plane * LRN;
    int t = threadIdx.x;
    for (int i = t; i < LRN; i += 256) { As[i] = Ap[i]; Bs[i] = Bp[i]; }
    __syncthreads();
    const float* ep = enc + (size_t)plane * PLN;
    const float* dp = dec + (size_t)plane * PLN;
    float*       op = out + (size_t)plane * PLN;
    int xg = t & 63, ys = t >> 6;
    int cm = max(xg - 1, 0), cp = min(xg + 1, 63);
    for (int yy = 0; yy < 64; yy++) {
        int y = yy*4 + ys;
        float sy = fmaxf((float)y * 0.25f - 0.375f, 0.0f);
        int y0 = (int)sy;
        float wy = sy - (float)y0;
        int y1 = min(y0 + 1, 63);
        const float* rA0 = As + y0*64; const float* rA1 = As + y1*64;
        const float* rB0 = Bs + y0*64; const float* rB1 = Bs + y1*64;
        float am = rA0[cm] + wy * (rA1[cm] - rA0[cm]);
        float ac = rA0[xg] + wy * (rA1[xg] - rA0[xg]);
        float ap = rA0[cp] + wy * (rA1[cp] - rA0[cp]);
        float bm = rB0[cm] + wy * (rB1[cm] - rB0[cm]);
        float bc = rB0[xg] + wy * (rB1[xg] - rB0[xg]);
        float bp = rB0[cp] + wy * (rB1[cp] - rB0[cp]);
        float A0, A1, B0v, B1v;
        if (xg == 0) { A0 = ac; A1 = ac; B0v = bc; B1v = bc; }  // src clamped to 0, w=0
        else {
            A0  = am + 0.625f * (ac - am);
            A1  = am + 0.875f * (ac - am);
            B0v = bm + 0.625f * (bc - bm);
            B1v = bm + 0.875f * (bc - bm);
        }
        float A2 = ac + 0.125f * (ap - ac), A3 = ac + 0.375f * (ap - ac);
        float B2 = bc + 0.125f * (bp - bc), B3 = bc + 0.375f * (bp - bc);
        size_t off = (size_t)y * WW + xg * 4;
        float4 e = *(const float4*)(ep + off);
        float4 d = *(const float4*)(dp + off);
        float4 o;
        o.x = d.x + A0 * e.x + B0v;
        o.y = d.y + A1 * e.y + B1v;
        o.z = d.z + A2 * e.z + B2;
        o.w = d.w + A3 * e.w + B3;
        *(float4*)(op + off) = o;
    }
}

extern "C" void kernel_launch(void* const* d_in, const int* in_sizes, int n_in,
                              void* d_out, int out_size) {
    const float* F_enc = (const float*)d_in[0];
    const float* F_dec = (const float*)d_in[1];
    const float* w_rg  = (const float*)d_in[2];
    const float* w_rt  = (const float*)d_in[3];
    const float* w_ua  = (const float*)d_in[4];
    const float* w_ub  = (const float*)d_in[5];
    const float* eps   = (const float*)d_in[6];
    float* out = (float*)d_out;

    k_prep<<<64, 256>>>(w_rg, w_rt, w_ua, w_ub);
    k_ds_proj<<<dim3(64, 2, 2), 256>>>(F_enc, F_dec);
    k_noop<<<1, 32>>>();   // shifts ncu capture window toward k_fuse
    k_guided<<<BB*RR, 256>>>(eps);
    k_proj_rc<<<dim3(32, 16, 2), 256>>>();
    k_fuse<<<BB*CC, 256>>>(F_enc, F_dec, out);
}

// round 10
// speedup vs baseline: 1.0276x; 1.0158x over previous
#include <cuda_runtime.h>

#define BB 4
#define CC 256
#define HH 256
#define WW 256
#define RR 64
#define HL 64
#define WL 64
#define LRN (HL*WL)      // 4096
#define PLN (HH*WW)      // 65536

// Scratch (no allocation allowed -> device globals).
__device__ float g_fgp[2][BB*RR*LRN];   // 2 channel-group partials of fg
__device__ float g_ftp[2][BB*RR*LRN];   // 2 channel-group partials of ft
__device__ float g_a [BB*RR*LRN];
__device__ float g_bv[BB*RR*LRN];
__device__ float g_A [BB*CC*LRN];
__device__ float g_B [BB*CC*LRN];

typedef unsigned long long u64;

__device__ __forceinline__ u64 pack2(float lo, float hi) {
    u64 r; asm("mov.b64 %0, {%1, %2};" : "=l"(r) : "f"(lo), "f"(hi)); return r;
}
__device__ __forceinline__ void fma2(u64& d, u64 a, u64 b) {
    asm("fma.rn.f32x2 %0, %1, %2, %0;" : "+l"(d) : "l"(a), "l"(b));
}
__device__ __forceinline__ float2 unpk(u64 v) {
    float2 f; asm("mov.b64 {%0, %1}, %2;" : "=f"(f.x), "=f"(f.y) : "l"(v)); return f;
}

// K12 (fused): bilinear downsample 256->64 + partial C->R projection over a
// 128-channel group, staged GEMM with double-buffered ds tiles. (Proven R6.)
// Weights transposed on the fly from w (layout [R][C]) -> smem [c][r].
// grid: (64 px-blocks, 2 c-groups, 2 tensors), 256 threads, 48KB smem.
__global__ __launch_bounds__(256) void k_ds_proj(const float* __restrict__ enc,
                                                 const float* __restrict__ dec,
                                                 const float* __restrict__ wrg,
                                                 const float* __restrict__ wrt) {
    __shared__ float w_sm[128*RR];       // 32KB: [c_local][r]
    __shared__ float ds_sm[2][8*256];    // 2 x 8KB: [c_chunk_local][px_local]
    int cg = blockIdx.y;
    const float* in  = (blockIdx.z == 0) ? enc  : dec;
    const float* wt  = (blockIdx.z == 0) ? wrg  : wrt;   // [r][c] row-major
    float*       out = (blockIdx.z == 0) ? &g_fgp[cg][0] : &g_ftp[cg][0];
    int t = threadIdx.x;
    // Transposing fill: w_sm[c*64 + r] = wt[r*CC + cg*128 + c].
    for (int i = t; i < 128*RR; i += 256) {
        int c = i >> 6, r = i & 63;
        w_sm[i] = wt[r*CC + cg*128 + c];
    }

    int q = blockIdx.x * 256 + t;           // this thread's staging pixel
    int b = q >> 12, rest = q & 4095;
    int x = rest & 63, y = rest >> 6;
    const float* base = in + (size_t)b * CC * PLN + (size_t)cg * 128 * PLN
                           + (size_t)(4*y + 1) * WW + 4*x;

    int rg = t & 3, pg = t >> 2;            // GEMM role: 16 r's, 4 px's

    u64 acc[4][8];
    #pragma unroll
    for (int p = 0; p < 4; p++)
        #pragma unroll
        for (int j = 0; j < 8; j++) acc[p][j] = 0ull;

    for (int ch = 0; ch < 16; ch++) {       // 16 chunks of 8 channels
        int buf = ch & 1;
        #pragma unroll
        for (int cl = 0; cl < 8; cl++) {
            const float* p = base + (size_t)(ch*8 + cl) * PLN;
            float4 r0 = *(const float4*)p;
            float4 r1 = *(const float4*)(p + WW);
            ds_sm[buf][cl*256 + t] = 0.25f * ((r0.y + r0.z) + (r1.y + r1.z));
        }
        __syncthreads();
        #pragma unroll
        for (int cl = 0; cl < 8; cl++) {
            int c = ch*8 + cl;
            float4 d = *(const float4*)(ds_sm[buf] + cl*256 + pg*4);
            u64 d2[4];
            d2[0] = pack2(d.x, d.x); d2[1] = pack2(d.y, d.y);
            d2[2] = pack2(d.z, d.z); d2[3] = pack2(d.w, d.w);
            const ulonglong2* wp = (const ulonglong2*)(w_sm + c*RR + rg*16);
            #pragma unroll
            for (int jj = 0; jj < 4; jj++) {
                ulonglong2 wv = wp[jj];
                #pragma unroll
                for (int p = 0; p < 4; p++) {
                    fma2(acc[p][2*jj    ], wv.x, d2[p]);
                    fma2(acc[p][2*jj + 1], wv.y, d2[p]);
                }
            }
        }
    }
    int rest0 = (blockIdx.x * 256 + pg*4) & 4095;
    float* pout = out + (size_t)b * RR * LRN + rest0 + (size_t)(rg*16) * LRN;
    #pragma unroll
    for (int k = 0; k < 8; k++) {
        float2 u0 = unpk(acc[0][k]), u1 = unpk(acc[1][k]);
        float2 u2 = unpk(acc[2][k]), u3 = unpk(acc[3][k]);
        *(float4*)(pout + (size_t)(2*k    ) * LRN) = make_float4(u0.x, u1.x, u2.x, u3.x);
        *(float4*)(pout + (size_t)(2*k + 1) * LRN) = make_float4(u0.y, u1.y, u2.y, u3.y);
    }
}

// K3a: sum 2 channel-group partials, 3x3 zero-padded box mean (/9) + a,b.
// Split into y-halves for 2x parallelism: grid 512 = (b*RR + r) * 2 halves.
// Each block stages 34 rows (1-row zero-filled halo each side).
__global__ __launch_bounds__(256) void k_guided(const float* __restrict__ eps_p) {
    __shared__ float gs[34*64], ts[34*64];
    int pl   = blockIdx.x >> 1;     // b*RR + r
    int half = blockIdx.x & 1;
    int y0   = half * 32;
    size_t off = (size_t)pl * LRN;
    int t = threadIdx.x;
    for (int i = t; i < 34*64; i += 256) {
        int ry = (i >> 6) + y0 - 1;
        float gv = 0.f, tv = 0.f;
        if (ry >= 0 && ry < 64) {
            int idx = ry*64 + (i & 63);
            gv = g_fgp[0][off+idx] + g_fgp[1][off+idx];
            tv = g_ftp[0][off+idx] + g_ftp[1][off+idx];
        }
        gs[i] = gv; ts[i] = tv;
    }
    __syncthreads();
    float eps = *eps_p;
    const float inv9 = 1.0f / 9.0f;
    for (int i = t; i < 32*64; i += 256) {
        int yl = (i >> 6) + 1;      // smem row (halo offset)
        int x  = i & 63;
        float sg = 0.f, st = 0.f, sgg = 0.f, sgt = 0.f;
        #pragma unroll
        for (int dy = -1; dy <= 1; dy++) {
            const float* gr = gs + (yl+dy)*64;
            const float* tr = ts + (yl+dy)*64;
            #pragma unroll
            for (int dx = -1; dx <= 1; dx++) {
                int xx = x + dx;
                if (xx < 0 || xx > 63) continue;
                float g = gr[xx], v = tr[xx];
                sg += g; st += v; sgg += g*g; sgt += g*v;
            }
        }
        float mg  = sg  * inv9, mt = st * inv9;
        float var = sgg * inv9 - mg*mg;
        float cov = sgt * inv9 - mg*mt;
        float a  = cov / (var + eps);
        float bv = mt - a * mg;
        int oidx = (y0 + (i >> 6))*64 + x;
        g_a [off + oidx] = a;
        g_bv[off + oidx] = bv;
    }
}

// K3b: R=64 -> C=256 projection at low-res. px-tile=2, o-tile=16,
// A/B split across blockIdx.z (proven R7: 38.1us). Weights loaded directly
// from w_ua/w_ub (layout [C][R]) -> smem [r][j].
__global__ __launch_bounds__(256) void k_proj_rc(const float* __restrict__ wua,
                                                 const float* __restrict__ wub) {
    __shared__ float w_sm[RR*16];
    const float* wt  = (blockIdx.z == 0) ? wua  : wub;   // [o][r] row-major
    const float* src = (blockIdx.z == 0) ? g_a  : g_bv;
    float*       dst = (blockIdx.z == 0) ? g_A  : g_B;
    int o0 = blockIdx.y * 16;
    int t = threadIdx.x;
    for (int i = t; i < RR*16; i += 256) {
        int r = i >> 4, j = i & 15;
        w_sm[i] = wt[(o0 + j)*RR + r];
    }
    __syncthreads();
    int q = (blockIdx.x * 256 + t) * 2;     // 2 consecutive pixels
    int b = q >> 12, rest = q & 4095;
    const float* ps = src + (size_t)b * RR * LRN + rest;
    u64 acc0[8], acc1[8];
    #pragma unroll
    for (int j = 0; j < 8; j++) { acc0[j]=0ull; acc1[j]=0ull; }
    #pragma unroll 4
    for (int r = 0; r < RR; r++) {
        float2 v = *(const float2*)(ps + (size_t)r * LRN);
        u64 v0 = pack2(v.x, v.x), v1 = pack2(v.y, v.y);
        const ulonglong2* wp = (const ulonglong2*)(w_sm + r*16);
        #pragma unroll
        for (int j = 0; j < 4; j++) {
            ulonglong2 w = wp[j];
            fma2(acc0[2*j  ], w.x, v0); fma2(acc1[2*j  ], w.x, v1);
            fma2(acc0[2*j+1], w.y, v0); fma2(acc1[2*j+1], w.y, v1);
        }
    }
    float* od = dst + (size_t)b * CC * LRN + rest;
    #pragma unroll
    for (int j = 0; j < 8; j++) {
        float2 u0 = unpk(acc0[j]), u1 = unpk(acc1[j]);
        *(float2*)(od + (size_t)(o0 + 2*j    ) * LRN) = make_float2(u0.x, u1.x);
        *(float2*)(od + (size_t)(o0 + 2*j + 1) * LRN) = make_float2(u0.y, u1.y);
    }
}

// K4: fused bilinear 64->256 upsample of A,B + out = F_dec + A*F_enc + B.
__global__ __launch_bounds__(256) void k_fuse(const float* __restrict__ enc,
                                              const float* __restrict__ dec,
                                              float* __restrict__ out) {
    __shared__ float As[LRN], Bs[LRN];
    int plane = blockIdx.x;
    const float* Ap = g_A + (size_t)plane * LRN;
    const float* Bp = g_B + (size_t)plane * LRN;
    int t = threadIdx.x;
    for (int i = t; i < LRN; i += 256) { As[i] = Ap[i]; Bs[i] = Bp[i]; }
    __syncthreads();
    const float* ep = enc + (size_t)plane * PLN;
    const float* dp = dec + (size_t)plane * PLN;
    float*       op = out + (size_t)plane * PLN;
    int xg = t & 63, ys = t >> 6;
    int cm = max(xg - 1, 0), cp = min(xg + 1, 63);
    for (int yy = 0; yy < 64; yy++) {
        int y = yy*4 + ys;
        float sy = fmaxf((float)y * 0.25f - 0.375f, 0.0f);
        int y0 = (int)sy;
        float wy = sy - (float)y0;
        int y1 = min(y0 + 1, 63);
        const float* rA0 = As + y0*64; const float* rA1 = As + y1*64;
        const float* rB0 = Bs + y0*64; const float* rB1 = Bs + y1*64;
        float am = rA0[cm] + wy * (rA1[cm] - rA0[cm]);
        float ac = rA0[xg] + wy * (rA1[xg] - rA0[xg]);
        float ap = rA0[cp] + wy * (rA1[cp] - rA0[cp]);
        float bm = rB0[cm] + wy * (rB1[cm] - rB0[cm]);
        float bc = rB0[xg] + wy * (rB1[xg] - rB0[xg]);
        float bp = rB0[cp] + wy * (rB1[cp] - rB0[cp]);
        float A0, A1, B0v, B1v;
        if (xg == 0) { A0 = ac; A1 = ac; B0v = bc; B1v = bc; }  // src clamped to 0, w=0
        else {
            A0  = am + 0.625f * (ac - am);
            A1  = am + 0.875f * (ac - am);
            B0v = bm + 0.625f * (bc - bm);
            B1v = bm + 0.875f * (bc - bm);
        }
        float A2 = ac + 0.125f * (ap - ac), A3 = ac + 0.375f * (ap - ac);
        float B2 = bc + 0.125f * (bp - bc), B3 = bc + 0.375f * (bp - bc);
        size_t off = (size_t)y * WW + xg * 4;
        float4 e = *(const float4*)(ep + off);
        float4 d = *(const float4*)(dp + off);
        float4 o;
        o.x = d.x + A0 * e.x + B0v;
        o.y = d.y + A1 * e.y + B1v;
        o.z = d.z + A2 * e.z + B2;
        o.w = d.w + A3 * e.w + B3;
        *(float4*)(op + off) = o;
    }
}

extern "C" void kernel_launch(void* const* d_in, const int* in_sizes, int n_in,
                              void* d_out, int out_size) {
    const float* F_enc = (const float*)d_in[0];
    const float* F_dec = (const float*)d_in[1];
    const float* w_rg  = (const float*)d_in[2];
    const float* w_rt  = (const float*)d_in[3];
    const float* w_ua  = (const float*)d_in[4];
    const float* w_ub  = (const float*)d_in[5];
    const float* eps   = (const float*)d_in[6];
    float* out = (float*)d_out;

    k_ds_proj<<<dim3(64, 2, 2), 256>>>(F_enc, F_dec, w_rg, w_rt);  // launch 1
    k_guided<<<BB*RR*2, 256>>>(eps);                                // launch 2
    k_proj_rc<<<dim3(32, 16, 2), 256>>>(w_ua, w_ub);                // launch 3
    k_fuse<<<BB*CC, 256>>>(F_enc, F_dec, out);                      // launch 4 -> ncu
}

// round 11
// speedup vs baseline: 1.1578x; 1.1267x over previous
#include <cuda_runtime.h>

#define BB 4
#define CC 256
#define HH 256
#define WW 256
#define RR 64
#define HL 64
#define WL 64
#define LRN (HL*WL)      // 4096
#define PLN (HH*WW)      // 65536

// Scratch (no allocation allowed -> device globals).
__device__ float g_fgp[2][BB*RR*LRN];   // 2 channel-group partials of fg
__device__ float g_ftp[2][BB*RR*LRN];   // 2 channel-group partials of ft
__device__ float g_a [BB*RR*LRN];
__device__ float g_bv[BB*RR*LRN];
__device__ float g_A [BB*CC*LRN];
__device__ float g_B [BB*CC*LRN];

typedef unsigned long long u64;

__device__ __forceinline__ u64 pack2(float lo, float hi) {
    u64 r; asm("mov.b64 %0, {%1, %2};" : "=l"(r) : "f"(lo), "f"(hi)); return r;
}
__device__ __forceinline__ void fma2(u64& d, u64 a, u64 b) {
    asm("fma.rn.f32x2 %0, %1, %2, %0;" : "+l"(d) : "l"(a), "l"(b));
}
__device__ __forceinline__ float2 unpk(u64 v) {
    float2 f; asm("mov.b64 {%0, %1}, %2;" : "=f"(f.x), "=f"(f.y) : "l"(v)); return f;
}

// K12 (fused): bilinear downsample 256->64 + partial C->R projection over a
// 128-channel group, staged GEMM with double-buffered ds tiles. (Proven R6.)
// Weights transposed on the fly from w (layout [R][C]) -> smem [c][r].
// grid: (64 px-blocks, 2 c-groups, 2 tensors), 256 threads, 48KB smem.
__global__ __launch_bounds__(256) void k_ds_proj(const float* __restrict__ enc,
                                                 const float* __restrict__ dec,
                                                 const float* __restrict__ wrg,
                                                 const float* __restrict__ wrt) {
    __shared__ float w_sm[128*RR];       // 32KB: [c_local][r]
    __shared__ float ds_sm[2][8*256];    // 2 x 8KB: [c_chunk_local][px_local]
    int cg = blockIdx.y;
    const float* in  = (blockIdx.z == 0) ? enc  : dec;
    const float* wt  = (blockIdx.z == 0) ? wrg  : wrt;   // [r][c] row-major
    float*       out = (blockIdx.z == 0) ? &g_fgp[cg][0] : &g_ftp[cg][0];
    int t = threadIdx.x;
    // Transposing fill: w_sm[c*64 + r] = wt[r*CC + cg*128 + c].
    for (int i = t; i < 128*RR; i += 256) {
        int c = i >> 6, r = i & 63;
        w_sm[i] = wt[r*CC + cg*128 + c];
    }

    int q = blockIdx.x * 256 + t;           // this thread's staging pixel
    int b = q >> 12, rest = q & 4095;
    int x = rest & 63, y = rest >> 6;
    const float* base = in + (size_t)b * CC * PLN + (size_t)cg * 128 * PLN
                           + (size_t)(4*y + 1) * WW + 4*x;

    int rg = t & 3, pg = t >> 2;            // GEMM role: 16 r's, 4 px's

    u64 acc[4][8];
    #pragma unroll
    for (int p = 0; p < 4; p++)
        #pragma unroll
        for (int j = 0; j < 8; j++) acc[p][j] = 0ull;

    for (int ch = 0; ch < 16; ch++) {       // 16 chunks of 8 channels
        int buf = ch & 1;
        #pragma unroll
        for (int cl = 0; cl < 8; cl++) {
            const float* p = base + (size_t)(ch*8 + cl) * PLN;
            float4 r0 = *(const float4*)p;
            float4 r1 = *(const float4*)(p + WW);
            ds_sm[buf][cl*256 + t] = 0.25f * ((r0.y + r0.z) + (r1.y + r1.z));
        }
        __syncthreads();
        #pragma unroll
        for (int cl = 0; cl < 8; cl++) {
            int c = ch*8 + cl;
            float4 d = *(const float4*)(ds_sm[buf] + cl*256 + pg*4);
            u64 d2[4];
            d2[0] = pack2(d.x, d.x); d2[1] = pack2(d.y, d.y);
            d2[2] = pack2(d.z, d.z); d2[3] = pack2(d.w, d.w);
            const ulonglong2* wp = (const ulonglong2*)(w_sm + c*RR + rg*16);
            #pragma unroll
            for (int jj = 0; jj < 4; jj++) {
                ulonglong2 wv = wp[jj];
                #pragma unroll
                for (int p = 0; p < 4; p++) {
                    fma2(acc[p][2*jj    ], wv.x, d2[p]);
                    fma2(acc[p][2*jj + 1], wv.y, d2[p]);
                }
            }
        }
    }
    int rest0 = (blockIdx.x * 256 + pg*4) & 4095;
    float* pout = out + (size_t)b * RR * LRN + rest0 + (size_t)(rg*16) * LRN;
    #pragma unroll
    for (int k = 0; k < 8; k++) {
        float2 u0 = unpk(acc[0][k]), u1 = unpk(acc[1][k]);
        float2 u2 = unpk(acc[2][k]), u3 = unpk(acc[3][k]);
        *(float4*)(pout + (size_t)(2*k    ) * LRN) = make_float4(u0.x, u1.x, u2.x, u3.x);
        *(float4*)(pout + (size_t)(2*k + 1) * LRN) = make_float4(u0.y, u1.y, u2.y, u3.y);
    }
}

// K3a: sum 2 channel-group partials, 3x3 zero-padded box mean (/9) + a,b.
// Split into y-halves: grid 512 = (b*RR + r) * 2 halves, 34-row halo tiles.
__global__ __launch_bounds__(256) void k_guided(const float* __restrict__ eps_p) {
    __shared__ float gs[34*64], ts[34*64];
    int pl   = blockIdx.x >> 1;     // b*RR + r
    int half = blockIdx.x & 1;
    int y0   = half * 32;
    size_t off = (size_t)pl * LRN;
    int t = threadIdx.x;
    for (int i = t; i < 34*64; i += 256) {
        int ry = (i >> 6) + y0 - 1;
        float gv = 0.f, tv = 0.f;
        if (ry >= 0 && ry < 64) {
            int idx = ry*64 + (i & 63);
            gv = g_fgp[0][off+idx] + g_fgp[1][off+idx];
            tv = g_ftp[0][off+idx] + g_ftp[1][off+idx];
        }
        gs[i] = gv; ts[i] = tv;
    }
    __syncthreads();
    float eps = *eps_p;
    const float inv9 = 1.0f / 9.0f;
    for (int i = t; i < 32*64; i += 256) {
        int yl = (i >> 6) + 1;      // smem row (halo offset)
        int x  = i & 63;
        float sg = 0.f, st = 0.f, sgg = 0.f, sgt = 0.f;
        #pragma unroll
        for (int dy = -1; dy <= 1; dy++) {
            const float* gr = gs + (yl+dy)*64;
            const float* tr = ts + (yl+dy)*64;
            #pragma unroll
            for (int dx = -1; dx <= 1; dx++) {
                int xx = x + dx;
                if (xx < 0 || xx > 63) continue;
                float g = gr[xx], v = tr[xx];
                sg += g; st += v; sgg += g*g; sgt += g*v;
            }
        }
        float mg  = sg  * inv9, mt = st * inv9;
        float var = sgg * inv9 - mg*mg;
        float cov = sgt * inv9 - mg*mt;
        float a  = cov / (var + eps);
        float bv = mt - a * mg;
        int oidx = (y0 + (i >> 6))*64 + x;
        g_a [off + oidx] = a;
        g_bv[off + oidx] = bv;
    }
}

// K3b: R=64 -> C=256 projection at low-res. px-tile=2, o-tile=16,
// A/B split across blockIdx.z (proven R7: 38.1us).
__global__ __launch_bounds__(256) void k_proj_rc(const float* __restrict__ wua,
                                                 const float* __restrict__ wub) {
    __shared__ float w_sm[RR*16];
    const float* wt  = (blockIdx.z == 0) ? wua  : wub;   // [o][r] row-major
    const float* src = (blockIdx.z == 0) ? g_a  : g_bv;
    float*       dst = (blockIdx.z == 0) ? g_A  : g_B;
    int o0 = blockIdx.y * 16;
    int t = threadIdx.x;
    for (int i = t; i < RR*16; i += 256) {
        int r = i >> 4, j = i & 15;
        w_sm[i] = wt[(o0 + j)*RR + r];
    }
    __syncthreads();
    int q = (blockIdx.x * 256 + t) * 2;     // 2 consecutive pixels
    int b = q >> 12, rest = q & 4095;
    const float* ps = src + (size_t)b * RR * LRN + rest;
    u64 acc0[8], acc1[8];
    #pragma unroll
    for (int j = 0; j < 8; j++) { acc0[j]=0ull; acc1[j]=0ull; }
    #pragma unroll 4
    for (int r = 0; r < RR; r++) {
        float2 v = *(const float2*)(ps + (size_t)r * LRN);
        u64 v0 = pack2(v.x, v.x), v1 = pack2(v.y, v.y);
        const ulonglong2* wp = (const ulonglong2*)(w_sm + r*16);
        #pragma unroll
        for (int j = 0; j < 4; j++) {
            ulonglong2 w = wp[j];
            fma2(acc0[2*j  ], w.x, v0); fma2(acc1[2*j  ], w.x, v1);
            fma2(acc0[2*j+1], w.y, v0); fma2(acc1[2*j+1], w.y, v1);
        }
    }
    float* od = dst + (size_t)b * CC * LRN + rest;
    #pragma unroll
    for (int j = 0; j < 8; j++) {
        float2 u0 = unpk(acc0[j]), u1 = unpk(acc1[j]);
        *(float2*)(od + (size_t)(o0 + 2*j    ) * LRN) = make_float2(u0.x, u1.x);
        *(float2*)(od + (size_t)(o0 + 2*j + 1) * LRN) = make_float2(u0.y, u1.y);
    }
}

// Per-y bilinear interp of A,B rows from smem (rows local to rbase).
__device__ __forceinline__ void interp_ab(const float* As, const float* Bs,
                                          int y, int rbase, int xg, int cm, int cp,
                                          float4& Av, float4& Bv) {
    float sy = fmaxf((float)y * 0.25f - 0.375f, 0.0f);
    int y0 = (int)sy;
    float wy = sy - (float)y0;
    int y1 = min(y0 + 1, 63);
    const float* rA0 = As + (y0 - rbase)*64; const float* rA1 = As + (y1 - rbase)*64;
    const float* rB0 = Bs + (y0 - rbase)*64; const float* rB1 = Bs + (y1 - rbase)*64;
    float am = rA0[cm] + wy * (rA1[cm] - rA0[cm]);
    float ac = rA0[xg] + wy * (rA1[xg] - rA0[xg]);
    float ap = rA0[cp] + wy * (rA1[cp] - rA0[cp]);
    float bm = rB0[cm] + wy * (rB1[cm] - rB0[cm]);
    float bc = rB0[xg] + wy * (rB1[xg] - rB0[xg]);
    float bp = rB0[cp] + wy * (rB1[cp] - rB0[cp]);
    if (xg == 0) { Av.x = ac; Av.y = ac; Bv.x = bc; Bv.y = bc; }   // src clamp, w=0
    else {
        Av.x = am + 0.625f * (ac - am);
        Av.y = am + 0.875f * (ac - am);
        Bv.x = bm + 0.625f * (bc - bm);
        Bv.y = bm + 0.875f * (bc - bm);
    }
    Av.z = ac + 0.125f * (ap - ac); Av.w = ac + 0.375f * (ap - ac);
    Bv.z = bc + 0.125f * (bp - bc); Bv.w = bc + 0.375f * (bp - bc);
}

// K4: fused bilinear 64->256 upsample of A,B + out = F_dec + A*F_enc + B.
// grid (BB*CC, 2): y-halves per plane; 33-row lowres tiles (17KB smem).
// Unroll-by-2 with load-first scheduling for MLP=4.
__global__ __launch_bounds__(256) void k_fuse(const float* __restrict__ enc,
                                              const float* __restrict__ dec,
                                              float* __restrict__ out) {
    __shared__ float As[33*64], Bs[33*64];
    int plane = blockIdx.x;
    int half  = blockIdx.y;
    int rbase = half * 31;          // lowres rows rbase..rbase+32 cover this half
    const float* Ap = g_A + (size_t)plane * LRN + rbase*64;
    const float* Bp = g_B + (size_t)plane * LRN + rbase*64;
    int t = threadIdx.x;
    for (int i = t; i < 33*64; i += 256) { As[i] = Ap[i]; Bs[i] = Bp[i]; }
    __syncthreads();
    const float* ep = enc + (size_t)plane * PLN;
    const float* dp = dec + (size_t)plane * PLN;
    float*       op = out + (size_t)plane * PLN;
    int xg = t & 63, ys = t >> 6;
    int cm = max(xg - 1, 0), cp = min(xg + 1, 63);
    int ybase = half*128 + ys;
    #pragma unroll
    for (int yy = 0; yy < 32; yy += 2) {
        int ya = ybase + yy*4;
        int yb = ya + 4;
        size_t offa = (size_t)ya * WW + xg * 4;
        size_t offb = (size_t)yb * WW + xg * 4;
        // Issue all 4 global loads before any dependent compute.
        float4 ea = *(const float4*)(ep + offa);
        float4 da = *(const float4*)(dp + offa);
        float4 eb = *(const float4*)(ep + offb);
        float4 db = *(const float4*)(dp + offb);
        float4 Aa, Ba, Ab, Bb;
        interp_ab(As, Bs, ya, rbase, xg, cm, cp, Aa, Ba);
        interp_ab(As, Bs, yb, rbase, xg, cm, cp, Ab, Bb);
        float4 oa, ob;
        oa.x = da.x + Aa.x * ea.x + Ba.x;
        oa.y = da.y + Aa.y * ea.y + Ba.y;
        oa.z = da.z + Aa.z * ea.z + Ba.z;
        oa.w = da.w + Aa.w * ea.w + Ba.w;
        ob.x = db.x + Ab.x * eb.x + Bb.x;
        ob.y = db.y + Ab.y * eb.y + Bb.y;
        ob.z = db.z + Ab.z * eb.z + Bb.z;
        ob.w = db.w + Ab.w * eb.w + Bb.w;
        *(float4*)(op + offa) = oa;
        *(float4*)(op + offb) = ob;
    }
}

extern "C" void kernel_launch(void* const* d_in, const int* in_sizes, int n_in,
                              void* d_out, int out_size) {
    const float* F_enc = (const float*)d_in[0];
    const float* F_dec = (const float*)d_in[1];
    const float* w_rg  = (const float*)d_in[2];
    const float* w_rt  = (const float*)d_in[3];
    const float* w_ua  = (const float*)d_in[4];
    const float* w_ub  = (const float*)d_in[5];
    const float* eps   = (const float*)d_in[6];
    float* out = (float*)d_out;

    k_ds_proj<<<dim3(64, 2, 2), 256>>>(F_enc, F_dec, w_rg, w_rt);  // launch 1
    k_guided<<<BB*RR*2, 256>>>(eps);                                // launch 2
    k_proj_rc<<<dim3(32, 16, 2), 256>>>(w_ua, w_ub);                // launch 3
    k_fuse<<<dim3(BB*CC, 2), 256>>>(F_enc, F_dec, out);             // launch 4 -> ncu
}

// round 12
// speedup vs baseline: 1.1983x; 1.0350x over previous
#include <cuda_runtime.h>

#define BB 4
#define CC 256
#define HH 256
#define WW 256
#define RR 64
#define HL 64
#define WL 64
#define LRN (HL*WL)      // 4096
#define PLN (HH*WW)      // 65536

// Scratch (no allocation allowed -> device globals).
__device__ float g_fgp[2][BB*RR*LRN];   // 2 channel-group partials of fg
__device__ float g_ftp[2][BB*RR*LRN];   // 2 channel-group partials of ft
__device__ float g_a [BB*RR*LRN];
__device__ float g_bv[BB*RR*LRN];
__device__ float g_A [BB*CC*LRN];
__device__ float g_B [BB*CC*LRN];

typedef unsigned long long u64;

__device__ __forceinline__ u64 pack2(float lo, float hi) {
    u64 r; asm("mov.b64 %0, {%1, %2};" : "=l"(r) : "f"(lo), "f"(hi)); return r;
}
__device__ __forceinline__ void fma2(u64& d, u64 a, u64 b) {
    asm("fma.rn.f32x2 %0, %1, %2, %0;" : "+l"(d) : "l"(a), "l"(b));
}
__device__ __forceinline__ float2 unpk(u64 v) {
    float2 f; asm("mov.b64 {%0, %1}, %2;" : "=f"(f.x), "=f"(f.y) : "l"(v)); return f;
}

// K12 (fused): bilinear downsample 256->64 + partial C->R projection over a
// 128-channel group. Software-pipelined: register-prefetch chunk ch+1's
// global loads BEFORE gemm(ch) so DRAM latency is covered by gemm issue.
// Per iter: STS prefetched chunk -> sync -> LDG next chunk -> gemm.
// grid: (64 px-blocks, 2 c-groups, 2 tensors), 256 threads, 40KB smem.
__global__ __launch_bounds__(256) void k_ds_proj(const float* __restrict__ enc,
                                                 const float* __restrict__ dec,
                                                 const float* __restrict__ wrg,
                                                 const float* __restrict__ wrt) {
    __shared__ float w_sm[128*RR];       // 32KB: [c_local][r]
    __shared__ float ds_sm[2][4*256];    // 2 x 4KB: [c_chunk_local][px_local]
    int cg = blockIdx.y;
    const float* in  = (blockIdx.z == 0) ? enc  : dec;
    const float* wt  = (blockIdx.z == 0) ? wrg  : wrt;   // [r][c] row-major
    float*       out = (blockIdx.z == 0) ? &g_fgp[cg][0] : &g_ftp[cg][0];
    int t = threadIdx.x;
    // Transposing fill: w_sm[c*64 + r] = wt[r*CC + cg*128 + c].
    for (int i = t; i < 128*RR; i += 256) {
        int c = i >> 6, r = i & 63;
        w_sm[i] = wt[r*CC + cg*128 + c];
    }

    int q = blockIdx.x * 256 + t;           // this thread's staging pixel
    int b = q >> 12, rest = q & 4095;
    int x = rest & 63, y = rest >> 6;
    const float* base = in + (size_t)b * CC * PLN + (size_t)cg * 128 * PLN
                           + (size_t)(4*y + 1) * WW + 4*x;

    int rg = t & 3, pg = t >> 2;            // GEMM role: 16 r's, 4 px's

    u64 acc[4][8];
    #pragma unroll
    for (int p = 0; p < 4; p++)
        #pragma unroll
        for (int j = 0; j < 8; j++) acc[p][j] = 0ull;

    // Prefetch chunk 0 into registers.
    float4 pre[4][2];
    #pragma unroll
    for (int cl = 0; cl < 4; cl++) {
        const float* p = base + (size_t)cl * PLN;
        pre[cl][0] = *(const float4*)p;
        pre[cl][1] = *(const float4*)(p + WW);
    }

    for (int ch = 0; ch < 32; ch++) {       // 32 chunks of 4 channels
        int buf = ch & 1;
        // Commit prefetched chunk to smem (waits on LDGs issued last iter,
        // whose latency was covered by last iter's gemm issue).
        #pragma unroll
        for (int cl = 0; cl < 4; cl++)
            ds_sm[buf][cl*256 + t] =
                0.25f * ((pre[cl][0].y + pre[cl][0].z) + (pre[cl][1].y + pre[cl][1].z));
        __syncthreads();   // also orders w_sm fill before first gemm (ch=0)
        // Issue next chunk's LDGs now — no consumer until next iteration.
        if (ch < 31) {
            #pragma unroll
            for (int cl = 0; cl < 4; cl++) {
                const float* p = base + (size_t)((ch + 1)*4 + cl) * PLN;
                pre[cl][0] = *(const float4*)p;
                pre[cl][1] = *(const float4*)(p + WW);
            }
        }
        // GEMM phase on committed buffer.
        #pragma unroll
        for (int cl = 0; cl < 4; cl++) {
            int c = ch*4 + cl;
            float4 d = *(const float4*)(ds_sm[buf] + cl*256 + pg*4);
            u64 d2[4];
            d2[0] = pack2(d.x, d.x); d2[1] = pack2(d.y, d.y);
            d2[2] = pack2(d.z, d.z); d2[3] = pack2(d.w, d.w);
            const ulonglong2* wp = (const ulonglong2*)(w_sm + c*RR + rg*16);
            #pragma unroll
            for (int jj = 0; jj < 4; jj++) {
                ulonglong2 wv = wp[jj];
                #pragma unroll
                for (int p = 0; p < 4; p++) {
                    fma2(acc[p][2*jj    ], wv.x, d2[p]);
                    fma2(acc[p][2*jj + 1], wv.y, d2[p]);
                }
            }
        }
        // Buffer-reuse safety: gemm(ch) precedes sync(ch+1) in program order,
        // and the overwrite of this buffer happens only after sync(ch+2)...
        // i.e. after sync(ch+1) — same invariant as the proven R6 scheme.
    }
    int rest0 = (blockIdx.x * 256 + pg*4) & 4095;
    float* pout = out + (size_t)b * RR * LRN + rest0 + (size_t)(rg*16) * LRN;
    #pragma unroll
    for (int k = 0; k < 8; k++) {
        float2 u0 = unpk(acc[0][k]), u1 = unpk(acc[1][k]);
        float2 u2 = unpk(acc[2][k]), u3 = unpk(acc[3][k]);
        *(float4*)(pout + (size_t)(2*k    ) * LRN) = make_float4(u0.x, u1.x, u2.x, u3.x);
        *(float4*)(pout + (size_t)(2*k + 1) * LRN) = make_float4(u0.y, u1.y, u2.y, u3.y);
    }
}

// K3a: sum 2 channel-group partials, 3x3 zero-padded box mean (/9) + a,b.
// Split into y-halves: grid 512 = (b*RR + r) * 2 halves, 34-row halo tiles.
__global__ __launch_bounds__(256) void k_guided(const float* __restrict__ eps_p) {
    __shared__ float gs[34*64], ts[34*64];
    int pl   = blockIdx.x >> 1;     // b*RR + r
    int half = blockIdx.x & 1;
    int y0   = half * 32;
    size_t off = (size_t)pl * LRN;
    int t = threadIdx.x;
    for (int i = t; i < 34*64; i += 256) {
        int ry = (i >> 6) + y0 - 1;
        float gv = 0.f, tv = 0.f;
        if (ry >= 0 && ry < 64) {
            int idx = ry*64 + (i & 63);
            gv = g_fgp[0][off+idx] + g_fgp[1][off+idx];
            tv = g_ftp[0][off+idx] + g_ftp[1][off+idx];
        }
        gs[i] = gv; ts[i] = tv;
    }
    __syncthreads();
    float eps = *eps_p;
    const float inv9 = 1.0f / 9.0f;
    for (int i = t; i < 32*64; i += 256) {
        int yl = (i >> 6) + 1;      // smem row (halo offset)
        int x  = i & 63;
        float sg = 0.f, st = 0.f, sgg = 0.f, sgt = 0.f;
        #pragma unroll
        for (int dy = -1; dy <= 1; dy++) {
            const float* gr = gs + (yl+dy)*64;
            const float* tr = ts + (yl+dy)*64;
            #pragma unroll
            for (int dx = -1; dx <= 1; dx++) {
                int xx = x + dx;
                if (xx < 0 || xx > 63) continue;
                float g = gr[xx], v = tr[xx];
                sg += g; st += v; sgg += g*g; sgt += g*v;
            }
        }
        float mg  = sg  * inv9, mt = st * inv9;
        float var = sgg * inv9 - mg*mg;
        float cov = sgt * inv9 - mg*mt;
        float a  = cov / (var + eps);
        float bv = mt - a * mg;
        int oidx = (y0 + (i >> 6))*64 + x;
        g_a [off + oidx] = a;
        g_bv[off + oidx] = bv;
    }
}

// K3b: R=64 -> C=256 projection at low-res. px-tile=2, o-tile=16,
// A/B split across blockIdx.z (proven R7: 38.1us).
__global__ __launch_bounds__(256) void k_proj_rc(const float* __restrict__ wua,
                                                 const float* __restrict__ wub) {
    __shared__ float w_sm[RR*16];
    const float* wt  = (blockIdx.z == 0) ? wua  : wub;   // [o][r] row-major
    const float* src = (blockIdx.z == 0) ? g_a  : g_bv;
    float*       dst = (blockIdx.z == 0) ? g_A  : g_B;
    int o0 = blockIdx.y * 16;
    int t = threadIdx.x;
    for (int i = t; i < RR*16; i += 256) {
        int r = i >> 4, j = i & 15;
        w_sm[i] = wt[(o0 + j)*RR + r];
    }
    __syncthreads();
    int q = (blockIdx.x * 256 + t) * 2;     // 2 consecutive pixels
    int b = q >> 12, rest = q & 4095;
    const float* ps = src + (size_t)b * RR * LRN + rest;
    u64 acc0[8], acc1[8];
    #pragma unroll
    for (int j = 0; j < 8; j++) { acc0[j]=0ull; acc1[j]=0ull; }
    #pragma unroll 4
    for (int r = 0; r < RR; r++) {
        float2 v = *(const float2*)(ps + (size_t)r * LRN);
        u64 v0 = pack2(v.x, v.x), v1 = pack2(v.y, v.y);
        const ulonglong2* wp = (const ulonglong2*)(w_sm + r*16);
        #pragma unroll
        for (int j = 0; j < 4; j++) {
            ulonglong2 w = wp[j];
            fma2(acc0[2*j  ], w.x, v0); fma2(acc1[2*j  ], w.x, v1);
            fma2(acc0[2*j+1], w.y, v0); fma2(acc1[2*j+1], w.y, v1);
        }
    }
    float* od = dst + (size_t)b * CC * LRN + rest;
    #pragma unroll
    for (int j = 0; j < 8; j++) {
        float2 u0 = unpk(acc0[j]), u1 = unpk(acc1[j]);
        *(float2*)(od + (size_t)(o0 + 2*j    ) * LRN) = make_float2(u0.x, u1.x);
        *(float2*)(od + (size_t)(o0 + 2*j + 1) * LRN) = make_float2(u0.y, u1.y);
    }
}

// Per-y bilinear interp of A,B rows from smem (rows local to rbase).
__device__ __forceinline__ void interp_ab(const float* As, const float* Bs,
                                          int y, int rbase, int xg, int cm, int cp,
                                          float4& Av, float4& Bv) {
    float sy = fmaxf((float)y * 0.25f - 0.375f, 0.0f);
    int y0 = (int)sy;
    float wy = sy - (float)y0;
    int y1 = min(y0 + 1, 63);
    const float* rA0 = As + (y0 - rbase)*64; const float* rA1 = As + (y1 - rbase)*64;
    const float* rB0 = Bs + (y0 - rbase)*64; const float* rB1 = Bs + (y1 - rbase)*64;
    float am = rA0[cm] + wy * (rA1[cm] - rA0[cm]);
    float ac = rA0[xg] + wy * (rA1[xg] - rA0[xg]);
    float ap = rA0[cp] + wy * (rA1[cp] - rA0[cp]);
    float bm = rB0[cm] + wy * (rB1[cm] - rB0[cm]);
    float bc = rB0[xg] + wy * (rB1[xg] - rB0[xg]);
    float bp = rB0[cp] + wy * (rB1[cp] - rB0[cp]);
    if (xg == 0) { Av.x = ac; Av.y = ac; Bv.x = bc; Bv.y = bc; }   // src clamp, w=0
    else {
        Av.x = am + 0.625f * (ac - am);
        Av.y = am + 0.875f * (ac - am);
        Bv.x = bm + 0.625f * (bc - bm);
        Bv.y = bm + 0.875f * (bc - bm);
    }
    Av.z = ac + 0.125f * (ap - ac); Av.w = ac + 0.375f * (ap - ac);
    Bv.z = bc + 0.125f * (bp - bc); Bv.w = bc + 0.375f * (bp - bc);
}

// K4: fused bilinear 64->256 upsample of A,B + out = F_dec + A*F_enc + B.
// grid (BB*CC, 2): y-halves per plane; 33-row lowres tiles (17KB smem).
// Unroll-by-4 with load-first scheduling for MLP=8.
__global__ __launch_bounds__(256) void k_fuse(const float* __restrict__ enc,
                                              const float* __restrict__ dec,
                                              float* __restrict__ out) {
    __shared__ float As[33*64], Bs[33*64];
    int plane = blockIdx.x;
    int half  = blockIdx.y;
    int rbase = half * 31;          // lowres rows rbase..rbase+32 cover this half
    const float* Ap = g_A + (size_t)plane * LRN + rbase*64;
    const float* Bp = g_B + (size_t)plane * LRN + rbase*64;
    int t = threadIdx.x;
    for (int i = t; i < 33*64; i += 256) { As[i] = Ap[i]; Bs[i] = Bp[i]; }
    __syncthreads();
    const float* ep = enc + (size_t)plane * PLN;
    const float* dp = dec + (size_t)plane * PLN;
    float*       op = out + (size_t)plane * PLN;
    int xg = t & 63, ys = t >> 6;
    int cm = max(xg - 1, 0), cp = min(xg + 1, 63);
    int ybase = half*128 + ys;
    #pragma unroll
    for (int yy = 0; yy < 32; yy += 4) {
        int yv[4]; size_t offv[4];
        float4 ev[4], dv[4];
        #pragma unroll
        for (int u = 0; u < 4; u++) {
            yv[u] = ybase + (yy + u)*4;
            offv[u] = (size_t)yv[u] * WW + xg * 4;
        }
        // Issue all 8 global loads before any dependent compute.
        #pragma unroll
        for (int u = 0; u < 4; u++) ev[u] = *(const float4*)(ep + offv[u]);
        #pragma unroll
        for (int u = 0; u < 4; u++) dv[u] = *(const float4*)(dp + offv[u]);
        #pragma unroll
        for (int u = 0; u < 4; u++) {
            float4 Av, Bv;
            interp_ab(As, Bs, yv[u], rbase, xg, cm, cp, Av, Bv);
            float4 o;
            o.x = dv[u].x + Av.x * ev[u].x + Bv.x;
            o.y = dv[u].y + Av.y * ev[u].y + Bv.y;
            o.z = dv[u].z + Av.z * ev[u].z + Bv.z;
            o.w = dv[u].w + Av.w * ev[u].w + Bv.w;
            *(float4*)(op + offv[u]) = o;
        }
    }
}

extern "C" void kernel_launch(void* const* d_in, const int* in_sizes, int n_in,
                              void* d_out, int out_size) {
    const float* F_enc = (const float*)d_in[0];
    const float* F_dec = (const float*)d_in[1];
    const float* w_rg  = (const float*)d_in[2];
    const float* w_rt  = (const float*)d_in[3];
    const float* w_ua  = (const float*)d_in[4];
    const float* w_ub  = (const float*)d_in[5];
    const float* eps   = (const float*)d_in[6];
    float* out = (float*)d_out;

    k_ds_proj<<<dim3(64, 2, 2), 256>>>(F_enc, F_dec, w_rg, w_rt);  // launch 1
    k_guided<<<BB*RR*2, 256>>>(eps);                                // launch 2
    k_proj_rc<<<dim3(32, 16, 2), 256>>>(w_ua, w_ub);                // launch 3
    k_fuse<<<dim3(BB*CC, 2), 256>>>(F_enc, F_dec, out);             // launch 4 -> ncu
}